// round 1
// baseline (speedup 1.0000x reference)
#include <cuda_runtime.h>
#include <cuda_bf16.h>

#define NKC 5000
#define BB  512
#define TT  100
#define THREADS 256

__device__ __forceinline__ float sigmoidf(float x) {
    return 1.0f / (1.0f + __expf(-x));
}

__global__ __launch_bounds__(THREADS)
void bkt_kernel(const int* __restrict__ prev_kc,
                const int* __restrict__ curr_kc,
                const int* __restrict__ prev_corr,
                const float* __restrict__ logits,
                float* __restrict__ out)
{
    __shared__ float sstate[NKC];            // per-batch skill state
    __shared__ float sA[TT], sB[TT], sP0[TT], sE[TT], sF[TT], sG[TT];
    __shared__ int   sPK[TT], sCK[TT];
    __shared__ float sprobs[TT];

    const int b   = blockIdx.x;
    const int tid = threadIdx.x;

    // ---- phase 1: init state = sigmoid(logits[:,4]) ----
    for (int k = tid; k < NKC; k += THREADS)
        sstate[k] = sigmoidf(logits[k * 5 + 4]);

    // ---- phase 2: per-step constants (state-independent) ----
    if (tid < TT) {
        const int s  = tid;
        const int ck = curr_kc[b * TT + s];
        const float c2 = sigmoidf(logits[ck * 5 + 2]);
        const float c3 = sigmoidf(logits[ck * 5 + 3]);
        sG[s]  = c2;
        sF[s]  = c3 - c2;
        sCK[s] = ck;
        if (s >= 1) {
            const int pk = prev_kc[b * TT + s];
            const int c  = prev_corr[b * TT + s];
            const float p0 = sigmoidf(logits[pk * 5 + 0]);
            const float p1 = sigmoidf(logits[pk * 5 + 1]);
            const float p2 = sigmoidf(logits[pk * 5 + 2]);
            const float p3 = sigmoidf(logits[pk * 5 + 3]);
            // p_out = pch^c * (1-pch)^(1-c) with c in {0,1} -> select
            const float po0 = c ? p2 : (1.0f - p2);
            const float po1 = c ? p3 : (1.0f - p3);
            sA[s]  = po1;                 // p_out[:,1]
            sB[s]  = po0;                 // p_out[:,0]
            sP0[s] = p0;
            sE[s]  = 1.0f - p1 - p0;      // predictive = p0 + E*filt
            sPK[s] = pk;
        }
    }
    __syncthreads();

    // ---- phase 3: serial recurrence (one thread) ----
    if (tid == 0) {
        // t = 0: no update, just read initial state
        float cs0 = sstate[sCK[0]];
        sprobs[0] = fmaf(sF[0], cs0, sG[0]);
        #pragma unroll 4
        for (int s = 1; s < TT; s++) {
            const int pk = sPK[s];
            const int ck = sCK[s];
            const float skill = sstate[pk];
            const float csraw = sstate[ck];      // issued early; select fixes ck==pk
            const float A = sA[s], B = sB[s];
            const float num  = A * skill;
            const float den  = fmaf(B, -skill, B) + num;   // B*(1-skill) + A*skill
            const float filt = __fdividef(num, den);
            const float pred = fmaf(sE[s], filt, sP0[s]);
            sstate[pk] = pred;
            const float cs = (ck == pk) ? pred : csraw;
            sprobs[s] = fmaf(sF[s], cs, sG[s]);
        }
    }
    __syncthreads();

    // ---- phase 4: writeback ----
    if (tid < TT)
        out[b * TT + tid] = sprobs[tid];

    float4*       dst = (float4*)(out + (size_t)BB * TT + (size_t)b * NKC);
    const float4* src = (const float4*)sstate;
    #pragma unroll 2
    for (int i = tid; i < NKC / 4; i += THREADS)
        dst[i] = src[i];
}

extern "C" void kernel_launch(void* const* d_in, const int* in_sizes, int n_in,
                              void* d_out, int out_size) {
    const int*   prev_kc   = (const int*)d_in[0];
    const int*   curr_kc   = (const int*)d_in[1];
    const int*   prev_corr = (const int*)d_in[2];
    const float* kc_logits = (const float*)d_in[3];
    float*       out       = (float*)d_out;

    bkt_kernel<<<BB, THREADS>>>(prev_kc, curr_kc, prev_corr, kc_logits, out);
}

// round 2
// speedup vs baseline: 1.1978x; 1.1978x over previous
#include <cuda_runtime.h>
#include <cuda_bf16.h>

#define NKC 5000
#define BB  512
#define TT  100
#define THREADS 256

__device__ float  g_c4[NKC];   // sigmoid(logits[:,4])  — initial state
__device__ float4 g_p4[NKC];   // sigmoid(logits[:,0..3])

__device__ __forceinline__ float sigmoidf(float x) {
    return 1.0f / (1.0f + __expf(-x));
}

__global__ void tbl_kernel(const float* __restrict__ logits) {
    int k = blockIdx.x * blockDim.x + threadIdx.x;
    if (k < NKC) {
        float s0 = sigmoidf(logits[k * 5 + 0]);
        float s1 = sigmoidf(logits[k * 5 + 1]);
        float s2 = sigmoidf(logits[k * 5 + 2]);
        float s3 = sigmoidf(logits[k * 5 + 3]);
        float s4 = sigmoidf(logits[k * 5 + 4]);
        g_p4[k] = make_float4(s0, s1, s2, s3);
        g_c4[k] = s4;
    }
}

__global__ __launch_bounds__(THREADS)
void bkt_kernel(const int* __restrict__ prev_kc,
                const int* __restrict__ curr_kc,
                const int* __restrict__ prev_corr,
                float* __restrict__ out)
{
    __shared__ float sstate[NKC];            // per-batch skill state
    __shared__ float sA[TT], sB[TT], sP0[TT], sE[TT], sF[TT], sG[TT];
    __shared__ int   sPK[TT], sCK[TT];
    __shared__ float sprobs[TT];

    const int b   = blockIdx.x;
    const int tid = threadIdx.x;

    // ---- phase 1: copy precomputed init state into smem (float4, L2 hits) ----
    {
        const float4* src = (const float4*)g_c4;
        float4*       dst = (float4*)sstate;
        #pragma unroll
        for (int i = tid; i < NKC / 4; i += THREADS)
            dst[i] = src[i];
    }

    // ---- phase 2: per-step constants (state-independent), gathered from table ----
    if (tid < TT) {
        const int s  = tid;
        const int ck = curr_kc[b * TT + s];
        const float4 cp = g_p4[ck];
        sG[s]  = cp.z;
        sF[s]  = cp.w - cp.z;
        sCK[s] = ck;
        if (s >= 1) {
            const int pk = prev_kc[b * TT + s];
            const int c  = prev_corr[b * TT + s];
            const float4 pp = g_p4[pk];
            // p_out = pch^c * (1-pch)^(1-c) with c in {0,1} -> select
            const float po0 = c ? pp.z : (1.0f - pp.z);
            const float po1 = c ? pp.w : (1.0f - pp.w);
            sA[s]  = po1;                    // p_out[:,1]
            sB[s]  = po0;                    // p_out[:,0]
            sP0[s] = pp.x;
            sE[s]  = 1.0f - pp.y - pp.x;     // predictive = p0 + E*filt
            sPK[s] = pk;
        }
    }
    __syncthreads();

    // ---- phase 3: serial recurrence (one thread) ----
    if (tid == 0) {
        float cs0 = sstate[sCK[0]];
        sprobs[0] = fmaf(sF[0], cs0, sG[0]);
        #pragma unroll 4
        for (int s = 1; s < TT; s++) {
            const int pk = sPK[s];
            const int ck = sCK[s];
            const float skill = sstate[pk];
            const float csraw = sstate[ck];      // issued early; select fixes ck==pk
            const float A = sA[s], B = sB[s];
            const float num  = A * skill;
            const float den  = fmaf(B, -skill, B) + num;   // B*(1-skill) + A*skill
            const float filt = __fdividef(num, den);
            const float pred = fmaf(sE[s], filt, sP0[s]);
            sstate[pk] = pred;
            const float cs = (ck == pk) ? pred : csraw;
            sprobs[s] = fmaf(sF[s], cs, sG[s]);
        }
    }
    __syncthreads();

    // ---- phase 4: writeback ----
    if (tid < TT)
        out[b * TT + tid] = sprobs[tid];

    float4*       dst = (float4*)(out + (size_t)BB * TT + (size_t)b * NKC);
    const float4* src = (const float4*)sstate;
    #pragma unroll 2
    for (int i = tid; i < NKC / 4; i += THREADS)
        dst[i] = src[i];
}

extern "C" void kernel_launch(void* const* d_in, const int* in_sizes, int n_in,
                              void* d_out, int out_size) {
    const int*   prev_kc   = (const int*)d_in[0];
    const int*   curr_kc   = (const int*)d_in[1];
    const int*   prev_corr = (const int*)d_in[2];
    const float* kc_logits = (const float*)d_in[3];
    float*       out       = (float*)d_out;

    tbl_kernel<<<(NKC + 255) / 256, 256>>>(kc_logits);
    bkt_kernel<<<BB, THREADS>>>(prev_kc, curr_kc, prev_corr, out);
}

// round 3
// speedup vs baseline: 1.6391x; 1.3684x over previous
#include <cuda_runtime.h>
#include <cuda_bf16.h>

#define NKC 5000
#define BB  512
#define TT  100
#define THREADS 256

__device__ float  g_c4[NKC];   // sigmoid(logits[:,4])  — initial state
__device__ float4 g_p4[NKC];   // sigmoid(logits[:,0..3])

__device__ __forceinline__ float sigmoidf(float x) {
    return 1.0f / (1.0f + __expf(-x));
}

__global__ void tbl_kernel(const float* __restrict__ logits) {
    int k = blockIdx.x * blockDim.x + threadIdx.x;
    if (k < NKC) {
        float s0 = sigmoidf(logits[k * 5 + 0]);
        float s1 = sigmoidf(logits[k * 5 + 1]);
        float s2 = sigmoidf(logits[k * 5 + 2]);
        float s3 = sigmoidf(logits[k * 5 + 3]);
        float s4 = sigmoidf(logits[k * 5 + 4]);
        g_p4[k] = make_float4(s0, s1, s2, s3);
        g_c4[k] = s4;
    }
}

__global__ __launch_bounds__(THREADS)
void bkt_kernel(const int* __restrict__ prev_kc,
                const int* __restrict__ curr_kc,
                const int* __restrict__ prev_corr,
                float* __restrict__ out)
{
    __shared__ float sstate[NKC];
    __shared__ int   sPK[TT];
    __shared__ float sVal[TT];
    __shared__ int   sReady[TT];
    __shared__ int   sDone;

    const int b   = blockIdx.x;
    const int tid = threadIdx.x;

    // ---- load step data; per-thread constants stay in registers ----
    int   pk = -1, ck = -1;
    float A = 0.f, Bc = 0.f, P0 = 0.f, E = 0.f, F = 0.f, G = 0.f;
    float initSkill = 0.f, initCs = 0.f;

    if (tid < TT) {
        ck = curr_kc[b * TT + tid];
        pk = prev_kc[b * TT + tid];
        const int c = prev_corr[b * TT + tid];
        sPK[tid]    = (tid >= 1) ? pk : -1;   // step 0 performs no update
        sReady[tid] = 0;
        const float4 cp = g_p4[ck];
        G = cp.z;
        F = cp.w - cp.z;
        initCs = g_c4[ck];
        if (tid >= 1) {
            const float4 pp = g_p4[pk];
            A  = c ? pp.w : (1.0f - pp.w);    // p_out[:,1]
            Bc = c ? pp.z : (1.0f - pp.z);    // p_out[:,0]
            P0 = pp.x;
            E  = 1.0f - pp.y - pp.x;
            initSkill = g_c4[pk];
        }
    }
    if (tid == 0) sDone = 0;
    __syncthreads();

    // ---- dependency scan: one pass over sPK per thread ----
    int  pw = -1;        // last s' <  tid writing pk  (skill source)
    int  w  = -1;        // last s' <= tid writing ck  (probs source)
    bool isLast = true;  // no s' > tid writes pk
    if (tid < TT) {
        #pragma unroll 4
        for (int s = 1; s < TT; s++) {
            const int p = sPK[s];
            if (s < tid  && p == pk) pw = s;
            if (s <= tid && p == ck) w  = s;
            if (s > tid  && p == pk) isLast = false;
        }
    }
    __syncthreads();

    // ---- wavefront resolve: independent per-KC chains, depth ~1-2 ----
    bool need = (tid >= 1 && tid < TT);
    bool mine = false;
    float myVal = 0.f;
    for (int round = 0; round < TT; round++) {
        bool go = need && !mine && (pw < 0 || sReady[pw]);
        if (go) {
            const float skill = (pw < 0) ? initSkill : sVal[pw];
            const float num   = A * skill;
            const float den   = fmaf(Bc, -skill, Bc) + num;  // B*(1-skill)+A*skill
            const float filt  = __fdividef(num, den);
            myVal = fmaf(E, filt, P0);
            sVal[tid] = myVal;
        }
        __syncthreads();
        if (go) {
            sReady[tid] = 1;
            mine = true;
            atomicAdd(&sDone, 1);
        }
        __syncthreads();
        if (sDone == TT - 1) break;
        __syncthreads();
    }

    // ---- probs output ----
    if (tid < TT) {
        const float cs = (w < 0) ? initCs : sVal[w];
        out[b * TT + tid] = fmaf(F, cs, G);
    }

    // ---- bulk state: init copy (L2-hot) + scatter + stream out ----
    {
        const float4* src = (const float4*)g_c4;
        float4*       dst = (float4*)sstate;
        #pragma unroll
        for (int i = tid; i < NKC / 4; i += THREADS)
            dst[i] = src[i];
    }
    __syncthreads();
    if (tid >= 1 && tid < TT && isLast)
        sstate[pk] = myVal;
    __syncthreads();
    {
        float4*       dst = (float4*)(out + (size_t)BB * TT + (size_t)b * NKC);
        const float4* src = (const float4*)sstate;
        #pragma unroll 2
        for (int i = tid; i < NKC / 4; i += THREADS)
            dst[i] = src[i];
    }
}

extern "C" void kernel_launch(void* const* d_in, const int* in_sizes, int n_in,
                              void* d_out, int out_size) {
    const int*   prev_kc   = (const int*)d_in[0];
    const int*   curr_kc   = (const int*)d_in[1];
    const int*   prev_corr = (const int*)d_in[2];
    const float* kc_logits = (const float*)d_in[3];
    float*       out       = (float*)d_out;

    tbl_kernel<<<(NKC + 255) / 256, 256>>>(kc_logits);
    bkt_kernel<<<BB, THREADS>>>(prev_kc, curr_kc, prev_corr, out);
}